// round 16
// baseline (speedup 1.0000x reference)
#include <cuda_runtime.h>
#include <math.h>
#include <stdint.h>

// Problem constants: B=2, S=2048, C=64, F=64, K=3
#define Bn   2
#define Sn   2048
#define Cn   64
#define Fn   64
#define Kt   3
#define TS   16               // output s-rows per block
#define RMAX 32               // D-window rows staged (real window ~22 here)
#define CS   40               // xs stride: 40%32=8 -> A-frag reads are 32-bank bijections
#define WS   68               // W stride: 68%32=4 -> B-frag reads are 32-bank bijections
#define DS   100              // D stride: gather conflict-light
#define Mtot (Bn * Sn)        // 4096

// sbuf partition (floats). A-frag reads reach 63*40+31 = 2551 < 2560 (in-bounds).
#define XOFF  0               // xs_hi: 64*40 = 2560 floats
#define WOFF  2560            // W: 96*68 = 6528 floats; reused as D[32][100] (3200)
#define SBUF_FLOATS (WOFF + 96 * WS)   // 9088 floats = 36352 B

// m16n8k8 tf32 mma, D += A*B (C=D in place)
__device__ __forceinline__ void mma_tf32(float* c, const uint32_t* a, const uint32_t* b) {
    asm volatile(
        "mma.sync.aligned.m16n8k8.row.col.f32.tf32.tf32.f32 "
        "{%0,%1,%2,%3}, {%4,%5,%6,%7}, {%8,%9}, {%0,%1,%2,%3};"
        : "+f"(c[0]), "+f"(c[1]), "+f"(c[2]), "+f"(c[3])
        : "r"(a[0]), "r"(a[1]), "r"(a[2]), "r"(a[3]), "r"(b[0]), "r"(b[1]));
}
__device__ __forceinline__ uint32_t tf32_rna(float x) {
    uint32_t r; asm("cvt.rna.tf32.f32 %0, %1;" : "=r"(r) : "f"(x)); return r;
}

// Single fused kernel. grid (256, 2), 256 threads (8 warps, all active).
// Block = 16 s-rows x 32 features (half h). D window (32 rows x 96) via tf32 mma.
__global__ __launch_bounds__(256) void ddc_mma(
    const float* __restrict__ x,   // (B,S,C)
    const float* __restrict__ kw,  // (F,C,K)
    const float* __restrict__ ow,  // (F,)
    const void*  __restrict__ dilp,
    float*       __restrict__ out) // (B,S,F)
{
    __shared__ __align__(16) float sbuf[SBUF_FLOATS];
    float* xs  = sbuf + XOFF;
    float* wsm = sbuf + WOFF;

    const int tid = threadIdx.x;
    const int wy  = tid >> 5;             // warp 0..7
    const int tx  = tid & 31;
    const int h   = blockIdx.y;
    const int rq0 = blockIdx.x * TS;
    const int b   = rq0 >> 11;            // S = 2048
    const int s0  = rq0 & (Sn - 1);

    // --- dilation decode + per-lane offsets ---
    int dil = *(const int*)dilp;                                // int32/int64 LE
    if (dil < 1 || dil > 65536) dil = (int)(*(const float*)dilp);
    const int f = h * 32 + tx;
    float mo  = 0.5f * (float)Sn / (float)(dil * Kt);
    float off = -mo / (1.0f + expf(-ow[f]));                    // -sigmoid*max_off
    float fl  = floorf(off);
    const int   I = (int)fl;
    const float w = off - fl;

    int Imn = I, Imx = I;
    #pragma unroll
    for (int o = 16; o; o >>= 1) {
        Imn = min(Imn, __shfl_xor_sync(0xffffffffu, Imn, o));
        Imx = max(Imx, __shfl_xor_sync(0xffffffffu, Imx, o));
    }
    int lo = s0 + Imn - (Kt - 1) * dil; if (lo < 0) lo = 0;
    int hi = s0 + TS - 1 + Imx + 1;     if (hi > Sn - 1) hi = Sn - 1;
    const bool ok = (hi - lo + 1) <= RMAX;   // block-uniform

    if (ok) {
        // --- Stage x window (tf32-rounded), column-per-lane (coalesced LDG) ---
        {
            const int c  = tid & 63;
            const int rb = (tid >> 6) * 8;           // 0,8,16,24
            const float* xcol = x + (size_t)b * Sn * Cn + c;
            #pragma unroll
            for (int i = 0; i < 8; i++) {
                int gr = lo + rb + i; if (gr > Sn - 1) gr = Sn - 1;
                xs[c * CS + rb + i] = __uint_as_float(tf32_rna(xcol[(size_t)gr * Cn]));
            }
        }
        // --- Stage W (tf32-rounded): row n = k*32+fr holds kernel[h*32+fr][c][k] ---
        {
            const int fr2 = tid >> 3, mb = tid & 7;
            const float4* kw4 = (const float4*)(kw + (h * 32 + fr2) * (Cn * Kt));
            #pragma unroll
            for (int it = 0; it < 6; it++) {
                int m = mb + 8 * it;                 // < 48
                float4 v = kw4[m];
                int t = 4 * m;                       // t = c*3 + k
                #pragma unroll
                for (int e = 0; e < 4; e++) {
                    float val = (e == 0) ? v.x : (e == 1) ? v.y : (e == 2) ? v.z : v.w;
                    int tt = t + e, c = tt / 3, k = tt - 3 * c;
                    wsm[(k * 32 + fr2) * WS + c] = __uint_as_float(tf32_rna(val));
                }
            }
        }
        __syncthreads();

        // --- MMA: all 8 warps. mt = wy&1 (rows 16mt..+15), nq = wy>>1 (cols 24nq..+23) ---
        const int mt  = wy & 1;
        const int nq  = wy >> 1;              // 0..3
        const int gid = tx >> 2, tig = tx & 3;
        float acc[3][4];
        #pragma unroll
        for (int nt = 0; nt < 3; nt++)
            #pragma unroll
            for (int e = 0; e < 4; e++) acc[nt][e] = 0.0f;

        {
            const float* pa = xs + mt * 16 + gid;           // + ca*CS {+8}
            const float* pw = wsm + (nq * 24 + gid) * WS;   // + nt*8*WS + c
            #pragma unroll
            for (int kt = 0; kt < 8; kt++) {
                const int ca = kt * 8 + tig;       // A col (channel)
                uint32_t ah[4];
                ah[0] = __float_as_uint(pa[(ca    ) * CS    ]);
                ah[1] = __float_as_uint(pa[(ca    ) * CS + 8]);
                ah[2] = __float_as_uint(pa[(ca + 4) * CS    ]);
                ah[3] = __float_as_uint(pa[(ca + 4) * CS + 8]);
                #pragma unroll
                for (int nt = 0; nt < 3; nt++) {
                    uint32_t bb[2];
                    bb[0] = __float_as_uint(pw[nt * 8 * WS + ca    ]);
                    bb[1] = __float_as_uint(pw[nt * 8 * WS + ca + 4]);
                    mma_tf32(acc[nt], ah, bb);
                }
            }
        }
        __syncthreads();   // all W reads done before D overwrite

        // --- Dump D (32 x 96, stride 100) into wsm region ---
        float* D = wsm;
        {
            const int ra = mt * 16 + gid;
            #pragma unroll
            for (int nt = 0; nt < 3; nt++) {
                int col = nq * 24 + nt * 8 + 2 * tig;
                *(float2*)(D + (ra    ) * DS + col) = make_float2(acc[nt][0], acc[nt][1]);
                *(float2*)(D + (ra + 8) * DS + col) = make_float2(acc[nt][2], acc[nt][3]);
            }
        }
        __syncthreads();

        // --- Gather + lerp; warp wy -> s-rows 2wy..2wy+1; coalesced stores ---
        #pragma unroll
        for (int jj = 0; jj < 2; jj++) {
            int s = s0 + wy * 2 + jj;
            float y = 0.0f;
            #pragma unroll
            for (int k = 0; k < Kt; k++) {
                int i0  = s - k * dil + I;
                int i0c = min(max(i0,     0), Sn - 1);
                int i1c = min(max(i0 + 1, 0), Sn - 1);
                float d0 = D[(i0c - lo) * DS + k * 32 + tx];
                float d1 = D[(i1c - lo) * DS + k * 32 + tx];
                y += d0 + w * (d1 - d0);
            }
            out[(rq0 + wy * 2 + jj) * Fn + f] = y;
        }
    } else {
        // Correct fallback for pathological offset spread (never triggers here).
        for (int jj = 0; jj < 2; jj++) {
            int s = s0 + wy * 2 + jj;
            float y = 0.0f;
            for (int k = 0; k < Kt; k++) {
                int i0  = s - k * dil + I;
                int i0c = min(max(i0,     0), Sn - 1);
                int i1c = min(max(i0 + 1, 0), Sn - 1);
                float a0 = 0.0f, a1 = 0.0f;
                for (int c = 0; c < Cn; c++) {
                    float kk = kw[f * (Cn * Kt) + c * Kt + k];
                    a0 += x[(size_t)(b * Sn + i0c) * Cn + c] * kk;
                    a1 += x[(size_t)(b * Sn + i1c) * Cn + c] * kk;
                }
                y += a0 + w * (a1 - a0);
            }
            out[(rq0 + wy * 2 + jj) * Fn + f] = y;
        }
    }
}

extern "C" void kernel_launch(void* const* d_in, const int* in_sizes, int n_in,
                              void* d_out, int out_size)
{
    const float* x   = (const float*)d_in[0];   // (B,S,C) f32
    const float* kw  = (const float*)d_in[1];   // (F,C,K) f32
    const float* ow  = (const float*)d_in[2];   // (F,)    f32
    const void*  dil = d_in[3];                 // scalar dilation_rate

    dim3 grid(Mtot / TS, 2);
    ddc_mma<<<grid, 256>>>(x, kw, ow, dil, (float*)d_out);
}

// round 17
// speedup vs baseline: 1.0190x; 1.0190x over previous
#include <cuda_runtime.h>
#include <math.h>
#include <stdint.h>

// Problem constants: B=2, S=2048, C=64, F=64, K=3
#define Bn   2
#define Sn   2048
#define Cn   64
#define Fn   64
#define Kt   3
#define TS   32               // output s-rows per block
#define RMAX 40               // D-window rows staged (real window <= 38 here)
#define CS   40               // xs stride: 40%32=8 -> A-frag reads are 32-bank bijections
#define WS   68               // W stride: 68%32=4 -> B-frag reads are 32-bank bijections
#define DS   100              // D stride: gather conflict-light
#define Mtot (Bn * Sn)        // 4096

// sbuf partition (floats). m-tile 2 A-frag reads reach 63*40+47 = 2567 < 2576 (pad).
#define XOFF  0               // xs: 64*40 = 2560 used (+16 pad)
#define WOFF  2576            // W: 96*68 = 6528 floats; reused as D[48][100] (max idx 4795)
#define SBUF_FLOATS (WOFF + 96 * WS)   // 9104 floats = 36416 B (fits static)

// m16n8k8 tf32 mma, D += A*B (C=D in place)
__device__ __forceinline__ void mma_tf32(float* c, const uint32_t* a, const uint32_t* b) {
    asm volatile(
        "mma.sync.aligned.m16n8k8.row.col.f32.tf32.tf32.f32 "
        "{%0,%1,%2,%3}, {%4,%5,%6,%7}, {%8,%9}, {%0,%1,%2,%3};"
        : "+f"(c[0]), "+f"(c[1]), "+f"(c[2]), "+f"(c[3])
        : "r"(a[0]), "r"(a[1]), "r"(a[2]), "r"(a[3]), "r"(b[0]), "r"(b[1]));
}
__device__ __forceinline__ uint32_t tf32_rna(float x) {
    uint32_t r; asm("cvt.rna.tf32.f32 %0, %1;" : "=r"(r) : "f"(x)); return r;
}

// Single fused kernel. grid (128, 2), 256 threads (8 warps).
// Block = 32 s-rows x 32 features (half h). D window (<=40 real rows) x 96 via
// single-pass tf32 mma: D = tf32(x) * tf32(w)  (rel err ~3e-4, 3.4x margin).
__global__ __launch_bounds__(256) void ddc_mma(
    const float* __restrict__ x,   // (B,S,C)
    const float* __restrict__ kw,  // (F,C,K)
    const float* __restrict__ ow,  // (F,)
    const void*  __restrict__ dilp,
    float*       __restrict__ out) // (B,S,F)
{
    __shared__ __align__(16) float sbuf[SBUF_FLOATS];
    float* xs  = sbuf + XOFF;
    float* wsm = sbuf + WOFF;

    const int tid = threadIdx.x;
    const int wy  = tid >> 5;             // warp 0..7
    const int tx  = tid & 31;
    const int h   = blockIdx.y;
    const int rq0 = blockIdx.x * TS;
    const int b   = rq0 >> 11;            // S = 2048
    const int s0  = rq0 & (Sn - 1);

    // --- dilation decode + per-lane offsets ---
    int dil = *(const int*)dilp;                                // int32/int64 LE
    if (dil < 1 || dil > 65536) dil = (int)(*(const float*)dilp);
    const int f = h * 32 + tx;
    float mo  = 0.5f * (float)Sn / (float)(dil * Kt);
    float off = -mo / (1.0f + expf(-ow[f]));                    // -sigmoid*max_off
    float fl  = floorf(off);
    const int   I = (int)fl;
    const float w = off - fl;

    int Imn = I, Imx = I;
    #pragma unroll
    for (int o = 16; o; o >>= 1) {
        Imn = min(Imn, __shfl_xor_sync(0xffffffffu, Imn, o));
        Imx = max(Imx, __shfl_xor_sync(0xffffffffu, Imx, o));
    }
    int lo = s0 + Imn - (Kt - 1) * dil; if (lo < 0) lo = 0;
    int hi = s0 + TS - 1 + Imx + 1;     if (hi > Sn - 1) hi = Sn - 1;
    const bool ok = (hi - lo + 1) <= RMAX;   // block-uniform

    if (ok) {
        // --- Stage x window (tf32-rounded), column-per-lane (coalesced LDG) ---
        {
            const int c  = tid & 63;
            const int rb = (tid >> 6) * 10;          // 0,10,20,30
            const float* xcol = x + (size_t)b * Sn * Cn + c;
            #pragma unroll
            for (int i = 0; i < 10; i++) {
                int gr = lo + rb + i; if (gr > Sn - 1) gr = Sn - 1;
                xs[c * CS + rb + i] = __uint_as_float(tf32_rna(xcol[(size_t)gr * Cn]));
            }
        }
        // --- Stage W (tf32-rounded): row n = k*32+fr holds kernel[h*32+fr][c][k] ---
        {
            const int fr2 = tid >> 3, mb = tid & 7;
            const float4* kw4 = (const float4*)(kw + (h * 32 + fr2) * (Cn * Kt));
            #pragma unroll
            for (int it = 0; it < 6; it++) {
                int m = mb + 8 * it;                 // < 48
                float4 v = kw4[m];
                int t = 4 * m;                       // t = c*3 + k
                #pragma unroll
                for (int e = 0; e < 4; e++) {
                    float val = (e == 0) ? v.x : (e == 1) ? v.y : (e == 2) ? v.z : v.w;
                    int tt = t + e, c = tt / 3, k = tt - 3 * c;
                    wsm[(k * 32 + fr2) * WS + c] = __uint_as_float(tf32_rna(val));
                }
            }
        }
        __syncthreads();

        // --- MMA single pass (warps 0..5): mt = wy>>1 rows 16mt..+15, nh = wy&1 ---
        const int mt  = wy >> 1;
        const int nh  = wy & 1;
        const int gid = tx >> 2, tig = tx & 3;
        float acc[6][4];
        #pragma unroll
        for (int nt = 0; nt < 6; nt++)
            #pragma unroll
            for (int e = 0; e < 4; e++) acc[nt][e] = 0.0f;

        if (wy < 6) {
            const float* pa = xs + mt * 16 + gid;           // + ca*CS {+8}
            const float* pw = wsm + (nh * 48 + gid) * WS;   // + nt*8*WS + c
            #pragma unroll
            for (int kt = 0; kt < 8; kt++) {
                const int ca = kt * 8 + tig;       // A col (channel)
                uint32_t ah[4];
                ah[0] = __float_as_uint(pa[(ca    ) * CS    ]);
                ah[1] = __float_as_uint(pa[(ca    ) * CS + 8]);
                ah[2] = __float_as_uint(pa[(ca + 4) * CS    ]);
                ah[3] = __float_as_uint(pa[(ca + 4) * CS + 8]);
                #pragma unroll
                for (int nt = 0; nt < 6; nt++) {
                    uint32_t bb[2];
                    bb[0] = __float_as_uint(pw[nt * 8 * WS + ca    ]);
                    bb[1] = __float_as_uint(pw[nt * 8 * WS + ca + 4]);
                    mma_tf32(acc[nt], ah, bb);
                }
            }
        }
        __syncthreads();   // all W reads done before D overwrite

        // --- Dump D (rows 0..47; rows >=40 unused) into wsm region ---
        float* D = wsm;
        if (wy < 6) {
            const int ra = mt * 16 + gid;
            #pragma unroll
            for (int nt = 0; nt < 6; nt++) {
                int col = nh * 48 + nt * 8 + 2 * tig;
                *(float2*)(D + (ra    ) * DS + col) = make_float2(acc[nt][0], acc[nt][1]);
                *(float2*)(D + (ra + 8) * DS + col) = make_float2(acc[nt][2], acc[nt][3]);
            }
        }
        __syncthreads();

        // --- Gather + lerp; warp wy -> s-rows 4wy..4wy+3; coalesced stores ---
        #pragma unroll
        for (int jj = 0; jj < 4; jj++) {
            int s = s0 + wy * 4 + jj;
            float y = 0.0f;
            #pragma unroll
            for (int k = 0; k < Kt; k++) {
                int i0  = s - k * dil + I;
                int i0c = min(max(i0,     0), Sn - 1);
                int i1c = min(max(i0 + 1, 0), Sn - 1);
                float d0 = D[(i0c - lo) * DS + k * 32 + tx];   // rows <= 39: real data
                float d1 = D[(i1c - lo) * DS + k * 32 + tx];
                y += d0 + w * (d1 - d0);
            }
            out[(rq0 + wy * 4 + jj) * Fn + f] = y;
        }
    } else {
        // Correct fallback for pathological offset spread (never triggers here).
        for (int jj = 0; jj < 4; jj++) {
            int s = s0 + wy * 4 + jj;
            float y = 0.0f;
            for (int k = 0; k < Kt; k++) {
                int i0  = s - k * dil + I;
                int i0c = min(max(i0,     0), Sn - 1);
                int i1c = min(max(i0 + 1, 0), Sn - 1);
                float a0 = 0.0f, a1 = 0.0f;
                for (int c = 0; c < Cn; c++) {
                    float kk = kw[f * (Cn * Kt) + c * Kt + k];
                    a0 += x[(size_t)(b * Sn + i0c) * Cn + c] * kk;
                    a1 += x[(size_t)(b * Sn + i1c) * Cn + c] * kk;
                }
                y += a0 + w * (a1 - a0);
            }
            out[(rq0 + wy * 4 + jj) * Fn + f] = y;
        }
    }
}

extern "C" void kernel_launch(void* const* d_in, const int* in_sizes, int n_in,
                              void* d_out, int out_size)
{
    const float* x   = (const float*)d_in[0];   // (B,S,C) f32
    const float* kw  = (const float*)d_in[1];   // (F,C,K) f32
    const float* ow  = (const float*)d_in[2];   // (F,)    f32
    const void*  dil = d_in[3];                 // scalar dilation_rate

    dim3 grid(Mtot / TS, 2);
    ddc_mma<<<grid, 256>>>(x, kw, ow, dil, (float*)d_out);
}